// round 8
// baseline (speedup 1.0000x reference)
#include <cuda_runtime.h>

#define NSP  13824      // 24^3
#define NPAD 17576      // 26^3
#define CCH  64
#define BB   2
#define NBLK_GATE 432   // 13824/32
#define GATE_BLOCKS (BB*NBLK_GATE)
#define QSC 0.18033688011112042f    // (1/8)*log2(e)

// scratch (zero-initialized at module load; padded borders of g_xk/g_xv stay 0 forever)
__device__ float g_xq[BB*CCH*NSP];
__device__ float g_xk[BB*CCH*NPAD];
__device__ float g_xv[BB*CCH*NPAD];
__device__ float g_attn[BB*CCH*NSP];
__device__ float g_part[BB*CCH*NBLK_GATE];   // [(b*64+o)*432 + blk]
__device__ int   g_cnt;                      // zero-init; last gate block resets each launch

__device__ __forceinline__ float ex2f_(float x){ float y; asm("ex2.approx.ftz.f32 %0, %1;":"=f"(y):"f"(x)); return y; }
__device__ __forceinline__ float rcpf_(float x){ float y; asm("rcp.approx.ftz.f32 %0, %1;":"=f"(y):"f"(x)); return y; }
__device__ __forceinline__ float sigmf_(float x){ return rcpf_(1.f + ex2f_(-1.44269504f*x)); }

// packed f32x2 helpers (FFMA2 — only reachable via PTX fma.rn.f32x2)
__device__ __forceinline__ unsigned long long pack2_(float a, float b){
    unsigned long long r; asm("mov.b64 %0, {%1, %2};" : "=l"(r) : "f"(a), "f"(b)); return r;
}
__device__ __forceinline__ unsigned long long packdup_(float a){
    unsigned long long r; asm("mov.b64 %0, {%1, %1};" : "=l"(r) : "f"(a)); return r;
}
__device__ __forceinline__ unsigned long long ffma2_(unsigned long long a, unsigned long long b, unsigned long long c){
    unsigned long long d; asm("fma.rn.f32x2 %0, %1, %2, %3;" : "=l"(d) : "l"(a), "l"(b), "l"(c)); return d;
}
__device__ __forceinline__ void unpack2_(unsigned long long p, float& a, float& b){
    asm("mov.b64 {%0, %1}, %2;" : "=f"(a), "=f"(b) : "l"(p));
}

// ---------------- Phase A: q/k/v projections ----------------
// grid (216 tiles, 2 batches, 3 passes), 64 threads; tile = 64 out x 64 pts,
// per-thread 8x8 with packed f32x2 accumulators.
__global__ __launch_bounds__(64) void proj_kernel(
    const float* __restrict__ x, const float* __restrict__ Wq, const float* __restrict__ bq,
    const float* __restrict__ Wk, const float* __restrict__ Wv)
{
    __shared__ float xs[64][64];
    __shared__ float Ws[64][65];
    int n0 = blockIdx.x*64, b = blockIdx.y, pass = blockIdx.z;
    int tid = threadIdx.x;
    const float* W = pass==0?Wq:(pass==1?Wk:Wv);

    const float* xb = x + (size_t)b*64*NSP + n0;
    for (int idx=tid; idx<1024; idx+=64){
        int c = idx>>4, p4 = (idx&15)<<2;
        *(float4*)&xs[c][p4] = *(const float4*)(xb + c*NSP + p4);
    }
    for (int idx=tid; idx<4096; idx+=64)
        Ws[idx>>6][idx&63] = W[idx];
    __syncthreads();

    int og = tid>>3, pg = tid&7;
    int pbase = pg<<3;
    unsigned long long acc[8][4];
    #pragma unroll
    for (int i=0;i<8;i++)
        #pragma unroll
        for (int j=0;j<4;j++) acc[i][j]=0ull;

    #pragma unroll 4
    for (int c=0;c<64;c++){
        float4 xa = *(const float4*)&xs[c][pbase];
        float4 xc = *(const float4*)&xs[c][pbase+4];
        unsigned long long xp[4];
        xp[0]=pack2_(xa.x,xa.y); xp[1]=pack2_(xa.z,xa.w);
        xp[2]=pack2_(xc.x,xc.y); xp[3]=pack2_(xc.z,xc.w);
        #pragma unroll
        for (int i=0;i<8;i++){
            unsigned long long wp = packdup_(Ws[og*8+i][c]);
            #pragma unroll
            for (int j=0;j<4;j++) acc[i][j] = ffma2_(wp, xp[j], acc[i][j]);
        }
    }

    if (pass==0){
        #pragma unroll
        for (int i=0;i<8;i++){
            int o = og*8+i;
            float bqv = __ldg(bq+o);
            float v[8];
            unpack2_(acc[i][0],v[0],v[1]); unpack2_(acc[i][1],v[2],v[3]);
            unpack2_(acc[i][2],v[4],v[5]); unpack2_(acc[i][3],v[6],v[7]);
            float4 s0, s1;
            s0.x=(v[0]+bqv)*QSC; s0.y=(v[1]+bqv)*QSC; s0.z=(v[2]+bqv)*QSC; s0.w=(v[3]+bqv)*QSC;
            s1.x=(v[4]+bqv)*QSC; s1.y=(v[5]+bqv)*QSC; s1.z=(v[6]+bqv)*QSC; s1.w=(v[7]+bqv)*QSC;
            float* dst = g_xq + (size_t)(b*64+o)*NSP + n0 + pbase;
            *(float4*)dst = s0; *(float4*)(dst+4) = s1;
        }
    } else {
        float* dstb = (pass==1)? g_xk : g_xv;
        int n = n0 + pbase;                      // 8-aligned, whole group in one 24-row
        int h=n/576, r=n-h*576, d=r/24, w=r-d*24;
        int np0=(h+1)*676+(d+1)*26+(w+1);
        #pragma unroll
        for (int i=0;i<8;i++){
            int o = og*8+i;
            float v[8];
            unpack2_(acc[i][0],v[0],v[1]); unpack2_(acc[i][1],v[2],v[3]);
            unpack2_(acc[i][2],v[4],v[5]); unpack2_(acc[i][3],v[6],v[7]);
            float* dst = dstb + (size_t)(b*64+o)*NPAD + np0;
            #pragma unroll
            for (int j=0;j<8;j++) dst[j]=v[j];
        }
    }
}

// ---------------- Phase B: per-channel scalar softmax attention (R2 version) ----------------
__global__ __launch_bounds__(256) void attn_kernel(
    const float* __restrict__ bk, const float* __restrict__ bv,
    const float* __restrict__ mk, const float* __restrict__ mv)
{
    int bc = blockIdx.y;              // b*64 + c
    int c  = bc & 63;
    int n  = blockIdx.x*256 + threadIdx.x;
    int h=n/576, r=n-h*576, d=r/24, w=r-d*24;
    int np=(h+1)*676+(d+1)*26+(w+1);
    float qs  = g_xq[bc*NSP+n];       // q * log2e/8
    float bkc = __ldg(bk+c), bvc = __ldg(bv+c);
    float qbk = qs*bkc;
    const float* Kp = g_xk + (size_t)bc*NPAD + np;
    const float* Vp = g_xv + (size_t)bc*NPAD + np;
    float den=0.f, num=0.f, dens=0.f;
    #pragma unroll
    for (int m=0;m<5;m++){
        float e = ex2f_(qs*__ldg(mk+c*5+m));
        den += e;
        num  = fmaf(e, __ldg(mv+c*5+m), num);
    }
    #pragma unroll
    for (int j=0;j<27;j++){
        int dz=j/9, rr=j-dz*9, dy=rr/3, dx=rr-dy*3;
        int off=(dz-1)*676+(dy-1)*26+(dx-1);
        float kv=__ldg(Kp+off), vv=__ldg(Vp+off);
        float e = ex2f_(fmaf(qs,kv,qbk));
        dens += e;
        num   = fmaf(e,vv,num);
    }
    num = fmaf(bvc,dens,num);
    g_attn[bc*NSP+n] = num * rcpf_(den+dens);
}

// ---------------- Phase C: gate + blend + fused GRU (last-block pattern) ----------------
__global__ __launch_bounds__(256) void gate_kernel(
    const float* __restrict__ x, const float* __restrict__ Wg,
    const float* __restrict__ bg, float* __restrict__ out,
    const float* __restrict__ prev, const float* __restrict__ Wih,
    const float* __restrict__ Whh, const float* __restrict__ bih,
    const float* __restrict__ bhh, float* __restrict__ out_mem)
{
    __shared__ float xs[64][33];
    __shared__ float as[64][33];
    __shared__ float Wb[64][65];
    __shared__ float ssum[64];
    __shared__ int   isLast;
    int b=blockIdx.y, n0=blockIdx.x*32, tid=threadIdx.x;
    if (tid<64) ssum[tid]=0.f;
    for (int i=tid;i<2048;i+=256){
        int cc=i>>5, nl=i&31;
        xs[cc][nl]=x[(b*64+cc)*NSP+n0+nl];
        as[cc][nl]=g_attn[(b*64+cc)*NSP+n0+nl];
    }
    int obase=(tid>>4)<<2, nb=(tid&15)<<1;
    float acc[4][2]={};
    for (int half=0;half<2;half++){
        __syncthreads();
        for (int i=tid;i<4096;i+=256) Wb[i>>6][i&63]=Wg[(i>>6)*128 + half*64 + (i&63)];
        __syncthreads();
        #pragma unroll 4
        for (int cc=0;cc<64;cc++){
            float s0 = half ? as[cc][nb]   : xs[cc][nb];
            float s1 = half ? as[cc][nb+1] : xs[cc][nb+1];
            #pragma unroll
            for (int i=0;i<4;i++){
                float wv=Wb[obase+i][cc];
                acc[i][0]=fmaf(wv,s0,acc[i][0]);
                acc[i][1]=fmaf(wv,s1,acc[i][1]);
            }
        }
    }
    #pragma unroll
    for (int i=0;i<4;i++){
        int o=obase+i;
        float bgo=__ldg(bg+o);
        float lsum=0.f;
        #pragma unroll
        for (int j=0;j<2;j++){
            float g  = sigmf_(acc[i][j]+bgo);
            float ov = g*as[o][nb+j] + (1.f-g)*xs[o][nb+j];
            out[(b*64+o)*NSP + n0+nb+j] = ov;
            lsum += ov;
        }
        atomicAdd(&ssum[o], lsum);
    }
    __syncthreads();
    if (tid<64) g_part[(b*64+tid)*NBLK_GATE + blockIdx.x] = ssum[tid];

    // ---- last-block GRU tail ----
    __threadfence();
    if (tid==0){
        int old = atomicAdd(&g_cnt, 1);
        isLast = (old == GATE_BLOCKS-1);
    }
    __syncthreads();
    if (!isLast) return;
    if (tid==0) g_cnt = 0;                    // reset for next graph replay

    __shared__ float red[256];
    __shared__ float mu[128], pm[128];
    {   // reduce partials: 2 threads per (b,o), fixed order -> deterministic
        int p = tid>>1, s = tid&1;
        const float* base = g_part + p*NBLK_GATE;
        float a0 = 0.f;
        #pragma unroll 4
        for (int i=s;i<NBLK_GATE;i+=2) a0 += base[i];
        red[tid] = a0;
    }
    if (tid<128) pm[tid] = prev[tid];
    __syncthreads();
    if (tid<128) mu[tid] = (red[tid*2]+red[tid*2+1]) * (1.f/13824.f);
    __syncthreads();

    int w = tid>>5, lane = tid&31;
    #pragma unroll
    for (int rep=0; rep<16; rep++){
        int p2 = w + rep*8;                   // 0..127
        int bb = p2>>6, o = p2&63;
        float a0=0.f,a1=0.f,a2=0.f,a3=0.f,a4=0.f,a5=0.f;
        #pragma unroll
        for (int half=0; half<2; half++){
            int cc = lane + half*32;
            float m  = mu[bb*64+cc];
            float pv = pm[bb*64+cc];
            a0 = fmaf(__ldg(Wih + o*64       + cc), m,  a0);
            a1 = fmaf(__ldg(Wih + (64+o)*64  + cc), m,  a1);
            a2 = fmaf(__ldg(Wih + (128+o)*64 + cc), m,  a2);
            a3 = fmaf(__ldg(Whh + o*64       + cc), pv, a3);
            a4 = fmaf(__ldg(Whh + (64+o)*64  + cc), pv, a4);
            a5 = fmaf(__ldg(Whh + (128+o)*64 + cc), pv, a5);
        }
        #pragma unroll
        for (int off=16; off; off>>=1){
            a0 += __shfl_xor_sync(0xffffffffu, a0, off);
            a1 += __shfl_xor_sync(0xffffffffu, a1, off);
            a2 += __shfl_xor_sync(0xffffffffu, a2, off);
            a3 += __shfl_xor_sync(0xffffffffu, a3, off);
            a4 += __shfl_xor_sync(0xffffffffu, a4, off);
            a5 += __shfl_xor_sync(0xffffffffu, a5, off);
        }
        if (lane==0 && out_mem){
            float gir = a0 + bih[o],     ghr = a3 + bhh[o];
            float giz = a1 + bih[64+o],  ghz = a4 + bhh[64+o];
            float gin = a2 + bih[128+o], ghn = a5 + bhh[128+o];
            float rg  = 1.f/(1.f+expf(-(gir+ghr)));
            float zg  = 1.f/(1.f+expf(-(giz+ghz)));
            float ng2 = tanhf(gin + rg*ghn);
            out_mem[p2] = (1.f-zg)*ng2 + zg*pm[bb*64+o];
        }
    }
}

extern "C" void kernel_launch(void* const* d_in, const int* in_sizes, int n_in,
                              void* d_out, int out_size)
{
    const float* x   = (const float*)d_in[0];
    const float* prev= (const float*)d_in[1];
    const float* Wq  = (const float*)d_in[2];
    const float* bq  = (const float*)d_in[3];
    const float* Wk  = (const float*)d_in[4];
    const float* bk  = (const float*)d_in[5];
    const float* Wv  = (const float*)d_in[6];
    const float* bv  = (const float*)d_in[7];
    const float* mk  = (const float*)d_in[8];
    const float* mv  = (const float*)d_in[9];
    const float* Wg  = (const float*)d_in[10];
    const float* bg  = (const float*)d_in[11];
    const float* Wih = (const float*)d_in[12];
    const float* Whh = (const float*)d_in[13];
    const float* bih = (const float*)d_in[14];
    const float* bhh = (const float*)d_in[15];
    float* out = (float*)d_out;
    float* out_mem = (out_size >= BB*CCH*NSP + BB*CCH) ? out + (size_t)BB*CCH*NSP : nullptr;

    proj_kernel<<<dim3(216,2,3),64>>>(x,Wq,bq,Wk,Wv);
    attn_kernel<<<dim3(54,128),256>>>(bk,bv,mk,mv);
    gate_kernel<<<dim3(NBLK_GATE,2),256>>>(x,Wg,bg,out,prev,Wih,Whh,bih,bhh,out_mem);
}

// round 10
// speedup vs baseline: 1.3173x; 1.3173x over previous
#include <cuda_runtime.h>

#define NSP  13824      // 24^3
#define NPAD 17576      // 26^3
#define CCH  64
#define BB   2
#define NBLK_GATE 432   // 13824/32
#define QSC 0.18033688011112042f    // (1/8)*log2(e)
#define FXS 16777216.0f             // 2^24 fixed-point scale

// scratch (zero-initialized at module load; padded borders of g_xk/g_xv stay 0 forever)
__device__ float g_xq[BB*CCH*NSP];
__device__ float g_xk[BB*CCH*NPAD];
__device__ float g_xv[BB*CCH*NPAD];
__device__ float g_attn[BB*CCH*NSP];
__device__ long long g_acc[BB*CCH];          // fixed-point channel sums; gru resets each launch

__device__ __forceinline__ float ex2f_(float x){ float y; asm("ex2.approx.ftz.f32 %0, %1;":"=f"(y):"f"(x)); return y; }
__device__ __forceinline__ float rcpf_(float x){ float y; asm("rcp.approx.ftz.f32 %0, %1;":"=f"(y):"f"(x)); return y; }
__device__ __forceinline__ float sigmf_(float x){ return rcpf_(1.f + ex2f_(-1.44269504f*x)); }

// ---------------- Phase A: q/k/v projections ----------------
// grid (216, 2, 3 passes), 128 threads; tile 64 out x 64 pts; per-thread 8o x 4p.
__global__ __launch_bounds__(128) void proj_kernel(
    const float* __restrict__ x, const float* __restrict__ Wq, const float* __restrict__ bq,
    const float* __restrict__ Wk, const float* __restrict__ Wv)
{
    __shared__ float xs[64][64];
    __shared__ float Ws[64][65];
    int n0 = blockIdx.x*64, b = blockIdx.y, pass = blockIdx.z;
    int tid = threadIdx.x;
    const float* W = pass==0?Wq:(pass==1?Wk:Wv);

    const float* xb = x + (size_t)(b*64)*NSP + n0;
    for (int i=tid;i<1024;i+=128){
        int c=i>>4, p4=(i&15)<<2;
        *(float4*)&xs[c][p4] = *(const float4*)(xb + (size_t)c*NSP + p4);
    }
    for (int i=tid;i<4096;i+=128) Ws[i>>6][i&63] = W[i];
    __syncthreads();

    int og = tid>>4;            // 8 groups of 8 outputs
    int pbase = (tid&15)<<2;    // 16 groups of 4 points
    float acc[8][4];
    #pragma unroll
    for (int i=0;i<8;i++){ acc[i][0]=0.f; acc[i][1]=0.f; acc[i][2]=0.f; acc[i][3]=0.f; }

    #pragma unroll 8
    for (int c=0;c<64;c++){
        float4 xr = *(const float4*)&xs[c][pbase];
        #pragma unroll
        for (int i=0;i<8;i++){
            float wv = Ws[og*8+i][c];
            acc[i][0]=fmaf(wv,xr.x,acc[i][0]);
            acc[i][1]=fmaf(wv,xr.y,acc[i][1]);
            acc[i][2]=fmaf(wv,xr.z,acc[i][2]);
            acc[i][3]=fmaf(wv,xr.w,acc[i][3]);
        }
    }

    if (pass==0){
        #pragma unroll
        for (int i=0;i<8;i++){
            int o = og*8+i;
            float bqv = __ldg(bq+o);
            float4 s;
            s.x=(acc[i][0]+bqv)*QSC; s.y=(acc[i][1]+bqv)*QSC;
            s.z=(acc[i][2]+bqv)*QSC; s.w=(acc[i][3]+bqv)*QSC;
            *(float4*)(g_xq + (size_t)(b*64+o)*NSP + n0 + pbase) = s;
        }
    } else {
        float* dstb = (pass==1)? g_xk : g_xv;
        int n = n0 + pbase;     // 4-aligned; 4-pt group never crosses a 24-row
        int h=n/576, r=n-h*576, d=r/24, w=r-d*24;
        int np0=(h+1)*676+(d+1)*26+(w+1);   // NOT 16B-aligned -> scalar stores only
        #pragma unroll
        for (int i=0;i<8;i++){
            int o = og*8+i;
            float* dst = dstb + (size_t)(b*64+o)*NPAD + np0;
            dst[0]=acc[i][0]; dst[1]=acc[i][1]; dst[2]=acc[i][2]; dst[3]=acc[i][3];
        }
    }
}

// ---------------- Phase B: per-channel scalar softmax attention (proven R2 version) ----------------
__global__ __launch_bounds__(256) void attn_kernel(
    const float* __restrict__ bk, const float* __restrict__ bv,
    const float* __restrict__ mk, const float* __restrict__ mv)
{
    int bc = blockIdx.y;              // b*64 + c
    int c  = bc & 63;
    int n  = blockIdx.x*256 + threadIdx.x;
    int h=n/576, r=n-h*576, d=r/24, w=r-d*24;
    int np=(h+1)*676+(d+1)*26+(w+1);
    float qs  = g_xq[bc*NSP+n];       // q * log2e/8
    float bkc = __ldg(bk+c), bvc = __ldg(bv+c);
    float qbk = qs*bkc;
    const float* Kp = g_xk + (size_t)bc*NPAD + np;
    const float* Vp = g_xv + (size_t)bc*NPAD + np;
    float den=0.f, num=0.f, dens=0.f;
    #pragma unroll
    for (int m=0;m<5;m++){
        float e = ex2f_(qs*__ldg(mk+c*5+m));
        den += e;
        num  = fmaf(e, __ldg(mv+c*5+m), num);
    }
    #pragma unroll
    for (int j=0;j<27;j++){
        int dz=j/9, rr=j-dz*9, dy=rr/3, dx=rr-dy*3;
        int off=(dz-1)*676+(dy-1)*26+(dx-1);
        float kv=__ldg(Kp+off), vv=__ldg(Vp+off);
        float e = ex2f_(fmaf(qs,kv,qbk));
        dens += e;
        num   = fmaf(e,vv,num);
    }
    num = fmaf(bvc,dens,num);
    g_attn[bc*NSP+n] = num * rcpf_(den+dens);
}

// ---------------- Phase C: gate + blend + fixed-point channel-sum atomics ----------------
__global__ __launch_bounds__(256) void gate_kernel(
    const float* __restrict__ x, const float* __restrict__ Wg,
    const float* __restrict__ bg, float* __restrict__ out)
{
    __shared__ float xs[64][33];
    __shared__ float as[64][33];
    __shared__ float Wb[64][65];
    __shared__ float ssum[64];
    int b=blockIdx.y, n0=blockIdx.x*32, tid=threadIdx.x;
    if (tid<64) ssum[tid]=0.f;
    for (int i=tid;i<2048;i+=256){
        int cc=i>>5, nl=i&31;
        xs[cc][nl]=x[(b*64+cc)*NSP+n0+nl];
        as[cc][nl]=g_attn[(b*64+cc)*NSP+n0+nl];
    }
    int obase=(tid>>4)<<2, nb=(tid&15)<<1;
    float acc[4][2]={};
    for (int half=0;half<2;half++){
        __syncthreads();
        for (int i=tid;i<4096;i+=256) Wb[i>>6][i&63]=Wg[(i>>6)*128 + half*64 + (i&63)];
        __syncthreads();
        #pragma unroll 4
        for (int cc=0;cc<64;cc++){
            float s0 = half ? as[cc][nb]   : xs[cc][nb];
            float s1 = half ? as[cc][nb+1] : xs[cc][nb+1];
            #pragma unroll
            for (int i=0;i<4;i++){
                float wv=Wb[obase+i][cc];
                acc[i][0]=fmaf(wv,s0,acc[i][0]);
                acc[i][1]=fmaf(wv,s1,acc[i][1]);
            }
        }
    }
    #pragma unroll
    for (int i=0;i<4;i++){
        int o=obase+i;
        float bgo=__ldg(bg+o);
        float lsum=0.f;
        #pragma unroll
        for (int j=0;j<2;j++){
            float g  = sigmf_(acc[i][j]+bgo);
            float ov = g*as[o][nb+j] + (1.f-g)*xs[o][nb+j];
            out[(b*64+o)*NSP + n0+nb+j] = ov;
            lsum += ov;
        }
        atomicAdd(&ssum[o], lsum);
    }
    __syncthreads();
    if (tid<64){
        long long q = (long long)llrintf(ssum[tid]*FXS);   // deterministic integer accumulation
        atomicAdd((unsigned long long*)&g_acc[b*64+tid], (unsigned long long)q);
    }
}

// ---------------- Phase D: GRU memory update (reads fixed-point sums, resets them) ----------------
__global__ __launch_bounds__(128) void gru_kernel(
    const float* __restrict__ prev, const float* __restrict__ Wih, const float* __restrict__ Whh,
    const float* __restrict__ bih, const float* __restrict__ bhh, float* __restrict__ out_mem)
{
    __shared__ float mu[128], pm[128];
    int tid = threadIdx.x;
    {
        mu[tid] = (float)((double)g_acc[tid] * (1.0/(16777216.0*13824.0)));
        pm[tid] = prev[tid];
    }
    __syncthreads();
    g_acc[tid] = 0;                           // reset for next graph replay

    int w = tid >> 5, lane = tid & 31;
    #pragma unroll
    for (int rep = 0; rep < 32; rep++){
        int p2 = w + rep*4;           // 0..127
        int b = p2 >> 6, o = p2 & 63;
        float a0=0.f,a1=0.f,a2=0.f,a3=0.f,a4=0.f,a5=0.f;
        #pragma unroll
        for (int half = 0; half < 2; half++){
            int cc = lane + half*32;
            float m  = mu[b*64+cc];
            float pv = pm[b*64+cc];
            a0 = fmaf(__ldg(Wih + o*64        + cc), m,  a0);
            a1 = fmaf(__ldg(Wih + (64+o)*64   + cc), m,  a1);
            a2 = fmaf(__ldg(Wih + (128+o)*64  + cc), m,  a2);
            a3 = fmaf(__ldg(Whh + o*64        + cc), pv, a3);
            a4 = fmaf(__ldg(Whh + (64+o)*64   + cc), pv, a4);
            a5 = fmaf(__ldg(Whh + (128+o)*64  + cc), pv, a5);
        }
        #pragma unroll
        for (int off = 16; off; off >>= 1){
            a0 += __shfl_xor_sync(0xffffffffu, a0, off);
            a1 += __shfl_xor_sync(0xffffffffu, a1, off);
            a2 += __shfl_xor_sync(0xffffffffu, a2, off);
            a3 += __shfl_xor_sync(0xffffffffu, a3, off);
            a4 += __shfl_xor_sync(0xffffffffu, a4, off);
            a5 += __shfl_xor_sync(0xffffffffu, a5, off);
        }
        if (lane == 0){
            float gir = a0 + bih[o],     ghr = a3 + bhh[o];
            float giz = a1 + bih[64+o],  ghz = a4 + bhh[64+o];
            float gin = a2 + bih[128+o], ghn = a5 + bhh[128+o];
            float rg  = 1.f/(1.f+expf(-(gir+ghr)));
            float zg  = 1.f/(1.f+expf(-(giz+ghz)));
            float ng2 = tanhf(gin + rg*ghn);
            out_mem[p2] = (1.f-zg)*ng2 + zg*pm[b*64+o];
        }
    }
}

extern "C" void kernel_launch(void* const* d_in, const int* in_sizes, int n_in,
                              void* d_out, int out_size)
{
    const float* x   = (const float*)d_in[0];
    const float* prev= (const float*)d_in[1];
    const float* Wq  = (const float*)d_in[2];
    const float* bq  = (const float*)d_in[3];
    const float* Wk  = (const float*)d_in[4];
    const float* bk  = (const float*)d_in[5];
    const float* Wv  = (const float*)d_in[6];
    const float* bv  = (const float*)d_in[7];
    const float* mk  = (const float*)d_in[8];
    const float* mv  = (const float*)d_in[9];
    const float* Wg  = (const float*)d_in[10];
    const float* bg  = (const float*)d_in[11];
    const float* Wih = (const float*)d_in[12];
    const float* Whh = (const float*)d_in[13];
    const float* bih = (const float*)d_in[14];
    const float* bhh = (const float*)d_in[15];
    float* out = (float*)d_out;

    proj_kernel<<<dim3(216,2,3),128>>>(x,Wq,bq,Wk,Wv);
    attn_kernel<<<dim3(54,128),256>>>(bk,bv,mk,mv);
    gate_kernel<<<dim3(NBLK_GATE,2),256>>>(x,Wg,bg,out);
    gru_kernel<<<1,128>>>(prev,Wih,Whh,bih,bhh,out + (size_t)BB*CCH*NSP);
}

// round 11
// speedup vs baseline: 1.4499x; 1.1006x over previous
#include <cuda_runtime.h>

#define NSP  13824      // 24^3
#define NPAD 17576      // 26^3
#define CCH  64
#define BB   2
#define NBLK_GATE 432   // 13824/32
#define QSC 0.18033688011112042f    // (1/8)*log2(e)
#define FXS 16777216.0f             // 2^24 fixed-point scale

// scratch (zero-initialized at module load; padded borders of g_xk/g_xv stay 0 forever)
__device__ float g_xq[BB*CCH*NSP];
__device__ float g_xk[BB*CCH*NPAD];
__device__ float g_xv[BB*CCH*NPAD];
__device__ float g_attn[BB*CCH*NSP];
__device__ long long g_acc[BB*CCH];          // fixed-point channel sums; gru resets each launch

__device__ __forceinline__ float ex2f_(float x){ float y; asm("ex2.approx.ftz.f32 %0, %1;":"=f"(y):"f"(x)); return y; }
__device__ __forceinline__ float rcpf_(float x){ float y; asm("rcp.approx.ftz.f32 %0, %1;":"=f"(y):"f"(x)); return y; }
__device__ __forceinline__ float sigmf_(float x){ return rcpf_(1.f + ex2f_(-1.44269504f*x)); }

// ---------------- Phase A: q/k/v projections ----------------
// grid (216, 2, 3 passes), 128 threads; tile 64 out x 64 pts; per-thread 8o x 4p.
__global__ __launch_bounds__(128) void proj_kernel(
    const float* __restrict__ x, const float* __restrict__ Wq, const float* __restrict__ bq,
    const float* __restrict__ Wk, const float* __restrict__ Wv)
{
    __shared__ float xs[64][64];
    __shared__ float Ws[64][65];
    int n0 = blockIdx.x*64, b = blockIdx.y, pass = blockIdx.z;
    int tid = threadIdx.x;
    const float* W = pass==0?Wq:(pass==1?Wk:Wv);

    const float* xb = x + (size_t)(b*64)*NSP + n0;
    for (int i=tid;i<1024;i+=128){
        int c=i>>4, p4=(i&15)<<2;
        *(float4*)&xs[c][p4] = *(const float4*)(xb + (size_t)c*NSP + p4);
    }
    for (int i=tid;i<4096;i+=128) Ws[i>>6][i&63] = W[i];
    __syncthreads();

    int og = tid>>4;            // 8 groups of 8 outputs
    int pbase = (tid&15)<<2;    // 16 groups of 4 points
    float acc[8][4];
    #pragma unroll
    for (int i=0;i<8;i++){ acc[i][0]=0.f; acc[i][1]=0.f; acc[i][2]=0.f; acc[i][3]=0.f; }

    #pragma unroll 8
    for (int c=0;c<64;c++){
        float4 xr = *(const float4*)&xs[c][pbase];
        #pragma unroll
        for (int i=0;i<8;i++){
            float wv = Ws[og*8+i][c];
            acc[i][0]=fmaf(wv,xr.x,acc[i][0]);
            acc[i][1]=fmaf(wv,xr.y,acc[i][1]);
            acc[i][2]=fmaf(wv,xr.z,acc[i][2]);
            acc[i][3]=fmaf(wv,xr.w,acc[i][3]);
        }
    }

    if (pass==0){
        #pragma unroll
        for (int i=0;i<8;i++){
            int o = og*8+i;
            float bqv = __ldg(bq+o);
            float4 s;
            s.x=(acc[i][0]+bqv)*QSC; s.y=(acc[i][1]+bqv)*QSC;
            s.z=(acc[i][2]+bqv)*QSC; s.w=(acc[i][3]+bqv)*QSC;
            *(float4*)(g_xq + (size_t)(b*64+o)*NSP + n0 + pbase) = s;
        }
    } else {
        float* dstb = (pass==1)? g_xk : g_xv;
        int n = n0 + pbase;     // 4-aligned; 4-pt group never crosses a 24-row
        int h=n/576, r=n-h*576, d=r/24, w=r-d*24;
        int np0=(h+1)*676+(d+1)*26+(w+1);   // NOT 16B-aligned -> scalar stores only
        #pragma unroll
        for (int i=0;i<8;i++){
            int o = og*8+i;
            float* dst = dstb + (size_t)(b*64+o)*NPAD + np0;
            dst[0]=acc[i][0]; dst[1]=acc[i][1]; dst[2]=acc[i][2]; dst[3]=acc[i][3];
        }
    }
}

// ---------------- Phase B: per-channel scalar softmax attention (proven R2 version) ----------------
__global__ __launch_bounds__(256) void attn_kernel(
    const float* __restrict__ bk, const float* __restrict__ bv,
    const float* __restrict__ mk, const float* __restrict__ mv)
{
    int bc = blockIdx.y;              // b*64 + c
    int c  = bc & 63;
    int n  = blockIdx.x*256 + threadIdx.x;
    int h=n/576, r=n-h*576, d=r/24, w=r-d*24;
    int np=(h+1)*676+(d+1)*26+(w+1);
    float qs  = g_xq[bc*NSP+n];       // q * log2e/8
    float bkc = __ldg(bk+c), bvc = __ldg(bv+c);
    float qbk = qs*bkc;
    const float* Kp = g_xk + (size_t)bc*NPAD + np;
    const float* Vp = g_xv + (size_t)bc*NPAD + np;
    float den=0.f, num=0.f, dens=0.f;
    #pragma unroll
    for (int m=0;m<5;m++){
        float e = ex2f_(qs*__ldg(mk+c*5+m));
        den += e;
        num  = fmaf(e, __ldg(mv+c*5+m), num);
    }
    #pragma unroll
    for (int j=0;j<27;j++){
        int dz=j/9, rr=j-dz*9, dy=rr/3, dx=rr-dy*3;
        int off=(dz-1)*676+(dy-1)*26+(dx-1);
        float kv=__ldg(Kp+off), vv=__ldg(Vp+off);
        float e = ex2f_(fmaf(qs,kv,qbk));
        dens += e;
        num   = fmaf(e,vv,num);
    }
    num = fmaf(bvc,dens,num);
    g_attn[bc*NSP+n] = num * rcpf_(den+dens);
}

// ---------------- Phase C: gate + blend + fixed-point channel-sum atomics ----------------
__global__ __launch_bounds__(256) void gate_kernel(
    const float* __restrict__ x, const float* __restrict__ Wg,
    const float* __restrict__ bg, float* __restrict__ out)
{
    __shared__ float xs[64][33];
    __shared__ float as[64][33];
    __shared__ float Wb[64][65];
    __shared__ float ssum[64];
    int b=blockIdx.y, n0=blockIdx.x*32, tid=threadIdx.x;
    if (tid<64) ssum[tid]=0.f;
    for (int i=tid;i<2048;i+=256){
        int cc=i>>5, nl=i&31;
        xs[cc][nl]=x[(b*64+cc)*NSP+n0+nl];
        as[cc][nl]=g_attn[(b*64+cc)*NSP+n0+nl];
    }
    int obase=(tid>>4)<<2, nb=(tid&15)<<1;
    float acc[4][2]={};
    for (int half=0;half<2;half++){
        __syncthreads();
        for (int i=tid;i<4096;i+=256) Wb[i>>6][i&63]=Wg[(i>>6)*128 + half*64 + (i&63)];
        __syncthreads();
        #pragma unroll 4
        for (int cc=0;cc<64;cc++){
            float s0 = half ? as[cc][nb]   : xs[cc][nb];
            float s1 = half ? as[cc][nb+1] : xs[cc][nb+1];
            #pragma unroll
            for (int i=0;i<4;i++){
                float wv=Wb[obase+i][cc];
                acc[i][0]=fmaf(wv,s0,acc[i][0]);
                acc[i][1]=fmaf(wv,s1,acc[i][1]);
            }
        }
    }
    #pragma unroll
    for (int i=0;i<4;i++){
        int o=obase+i;
        float bgo=__ldg(bg+o);
        float lsum=0.f;
        #pragma unroll
        for (int j=0;j<2;j++){
            float g  = sigmf_(acc[i][j]+bgo);
            float ov = g*as[o][nb+j] + (1.f-g)*xs[o][nb+j];
            out[(b*64+o)*NSP + n0+nb+j] = ov;
            lsum += ov;
        }
        atomicAdd(&ssum[o], lsum);
    }
    __syncthreads();
    if (tid<64){
        long long q = (long long)llrintf(ssum[tid]*FXS);   // deterministic integer accumulation
        atomicAdd((unsigned long long*)&g_acc[b*64+tid], (unsigned long long)q);
    }
}

// ---------------- Phase D: GRU memory update (1024 thr; reads fixed-point sums, resets) ----------------
__global__ __launch_bounds__(1024) void gru_kernel(
    const float* __restrict__ prev, const float* __restrict__ Wih, const float* __restrict__ Whh,
    const float* __restrict__ bih, const float* __restrict__ bhh, float* __restrict__ out_mem)
{
    __shared__ float mu[128], pm[128];
    int tid = threadIdx.x;
    if (tid < 128){
        mu[tid] = (float)((double)g_acc[tid] * (1.0/(16777216.0*13824.0)));
        pm[tid] = prev[tid];
    }
    __syncthreads();
    if (tid < 128) g_acc[tid] = 0;            // reset for next graph replay

    int w = tid >> 5, lane = tid & 31;
    #pragma unroll
    for (int rep = 0; rep < 4; rep++){
        int p2 = w + rep*32;          // 0..127
        int b = p2 >> 6, o = p2 & 63;
        float a0=0.f,a1=0.f,a2=0.f,a3=0.f,a4=0.f,a5=0.f;
        #pragma unroll
        for (int half = 0; half < 2; half++){
            int cc = lane + half*32;
            float m  = mu[b*64+cc];
            float pv = pm[b*64+cc];
            a0 = fmaf(__ldg(Wih + o*64        + cc), m,  a0);
            a1 = fmaf(__ldg(Wih + (64+o)*64   + cc), m,  a1);
            a2 = fmaf(__ldg(Wih + (128+o)*64  + cc), m,  a2);
            a3 = fmaf(__ldg(Whh + o*64        + cc), pv, a3);
            a4 = fmaf(__ldg(Whh + (64+o)*64   + cc), pv, a4);
            a5 = fmaf(__ldg(Whh + (128+o)*64  + cc), pv, a5);
        }
        #pragma unroll
        for (int off = 16; off; off >>= 1){
            a0 += __shfl_xor_sync(0xffffffffu, a0, off);
            a1 += __shfl_xor_sync(0xffffffffu, a1, off);
            a2 += __shfl_xor_sync(0xffffffffu, a2, off);
            a3 += __shfl_xor_sync(0xffffffffu, a3, off);
            a4 += __shfl_xor_sync(0xffffffffu, a4, off);
            a5 += __shfl_xor_sync(0xffffffffu, a5, off);
        }
        if (lane == 0){
            float gir = a0 + bih[o],     ghr = a3 + bhh[o];
            float giz = a1 + bih[64+o],  ghz = a4 + bhh[64+o];
            float gin = a2 + bih[128+o], ghn = a5 + bhh[128+o];
            float rg  = 1.f/(1.f+expf(-(gir+ghr)));
            float zg  = 1.f/(1.f+expf(-(giz+ghz)));
            float ng2 = tanhf(gin + rg*ghn);
            out_mem[p2] = (1.f-zg)*ng2 + zg*pm[b*64+o];
        }
    }
}

extern "C" void kernel_launch(void* const* d_in, const int* in_sizes, int n_in,
                              void* d_out, int out_size)
{
    const float* x   = (const float*)d_in[0];
    const float* prev= (const float*)d_in[1];
    const float* Wq  = (const float*)d_in[2];
    const float* bq  = (const float*)d_in[3];
    const float* Wk  = (const float*)d_in[4];
    const float* bk  = (const float*)d_in[5];
    const float* Wv  = (const float*)d_in[6];
    const float* bv  = (const float*)d_in[7];
    const float* mk  = (const float*)d_in[8];
    const float* mv  = (const float*)d_in[9];
    const float* Wg  = (const float*)d_in[10];
    const float* bg  = (const float*)d_in[11];
    const float* Wih = (const float*)d_in[12];
    const float* Whh = (const float*)d_in[13];
    const float* bih = (const float*)d_in[14];
    const float* bhh = (const float*)d_in[15];
    float* out = (float*)d_out;

    proj_kernel<<<dim3(216,2,3),128>>>(x,Wq,bq,Wk,Wv);
    attn_kernel<<<dim3(54,128),256>>>(bk,bv,mk,mv);
    gate_kernel<<<dim3(NBLK_GATE,2),256>>>(x,Wg,bg,out);
    gru_kernel<<<1,1024>>>(prev,Wih,Whh,bih,bhh,out + (size_t)BB*CCH*NSP);
}

// round 13
// speedup vs baseline: 1.4757x; 1.0178x over previous
#include <cuda_runtime.h>

#define NSP  13824      // 24^3
#define NPAD 17576      // 26^3
#define CCH  64
#define BB   2
#define NBLK_GATE 432   // 13824/32
#define QSC 0.18033688011112042f    // (1/8)*log2(e)
#define FXS 16777216.0f             // 2^24 fixed-point scale

// scratch (zero-initialized at module load; padded borders of g_xk/g_xv stay 0 forever)
__device__ float g_xq[BB*CCH*NSP];
__device__ float g_xk[BB*CCH*NPAD];
__device__ float g_xv[BB*CCH*NPAD];
__device__ float g_attn[BB*CCH*NSP];
__device__ long long g_acc[BB*CCH];          // fixed-point channel sums; gru resets each launch

__device__ __forceinline__ float ex2f_(float x){ float y; asm("ex2.approx.ftz.f32 %0, %1;":"=f"(y):"f"(x)); return y; }
__device__ __forceinline__ float rcpf_(float x){ float y; asm("rcp.approx.ftz.f32 %0, %1;":"=f"(y):"f"(x)); return y; }
__device__ __forceinline__ float sigmf_(float x){ return rcpf_(1.f + ex2f_(-1.44269504f*x)); }

// ---------------- Phase A: fused q/k/v projections ----------------
// grid (216, 2), 256 threads, dynamic smem: xs 16KB + 3 W matrices 48KB.
// All weights loaded ONCE, one sync, then 3 uninterrupted FFMA pass-loops.
__global__ __launch_bounds__(256) void proj_kernel(
    const float* __restrict__ x, const float* __restrict__ Wq, const float* __restrict__ bq,
    const float* __restrict__ Wk, const float* __restrict__ Wv)
{
    extern __shared__ float sm[];
    float (*xs)[64] = (float(*)[64])sm;                    // [64][64]
    float* Wall = sm + 4096;                               // [3][64][64]
    int n0 = blockIdx.x*64, b = blockIdx.y, tid = threadIdx.x;

    const float* xb = x + (size_t)(b*64)*NSP + n0;
    for (int i=tid;i<1024;i+=256){
        int c=i>>4, p4=(i&15)<<2;
        *(float4*)&xs[c][p4] = *(const float4*)(xb + (size_t)c*NSP + p4);
    }
    for (int i=tid;i<4096;i+=256){
        Wall[i]        = Wq[i];
        Wall[4096+i]   = Wk[i];
        Wall[8192+i]   = Wv[i];
    }
    __syncthreads();

    int og4 = (tid>>4)<<2;       // 16 groups of 4 outputs
    int pbase = (tid&15)<<2;     // 16 groups of 4 points

    // geometry for padded k/v stores (shared across passes 1,2)
    int n = n0 + pbase;          // 4-aligned, never crosses a 24-row
    int h=n/576, r=n-h*576, d=r/24, w=r-d*24;
    int np0=(h+1)*676+(d+1)*26+(w+1);   // NOT 16B-aligned -> scalar stores only

    #pragma unroll
    for (int pass=0; pass<3; pass++){
        const float* Wp = Wall + pass*4096;
        float acc[4][4];
        #pragma unroll
        for (int i=0;i<4;i++){ acc[i][0]=0.f; acc[i][1]=0.f; acc[i][2]=0.f; acc[i][3]=0.f; }

        #pragma unroll 8
        for (int c=0;c<64;c++){
            float4 xr = *(const float4*)&xs[c][pbase];
            #pragma unroll
            for (int i=0;i<4;i++){
                float wv = Wp[(og4+i)*64 + c];
                acc[i][0]=fmaf(wv,xr.x,acc[i][0]);
                acc[i][1]=fmaf(wv,xr.y,acc[i][1]);
                acc[i][2]=fmaf(wv,xr.z,acc[i][2]);
                acc[i][3]=fmaf(wv,xr.w,acc[i][3]);
            }
        }

        if (pass==0){
            #pragma unroll
            for (int i=0;i<4;i++){
                int o = og4+i;
                float bqv = __ldg(bq+o);
                float4 s;
                s.x=(acc[i][0]+bqv)*QSC; s.y=(acc[i][1]+bqv)*QSC;
                s.z=(acc[i][2]+bqv)*QSC; s.w=(acc[i][3]+bqv)*QSC;
                *(float4*)(g_xq + (size_t)(b*64+o)*NSP + n0 + pbase) = s;
            }
        } else {
            float* dstb = (pass==1)? g_xk : g_xv;
            #pragma unroll
            for (int i=0;i<4;i++){
                int o = og4+i;
                float* dst = dstb + (size_t)(b*64+o)*NPAD + np0;
                dst[0]=acc[i][0]; dst[1]=acc[i][1]; dst[2]=acc[i][2]; dst[3]=acc[i][3];
            }
        }
    }
}

// ---------------- Phase B: per-channel scalar softmax attention (proven R2 version) ----------------
__global__ __launch_bounds__(256) void attn_kernel(
    const float* __restrict__ bk, const float* __restrict__ bv,
    const float* __restrict__ mk, const float* __restrict__ mv)
{
    int bc = blockIdx.y;              // b*64 + c
    int c  = bc & 63;
    int n  = blockIdx.x*256 + threadIdx.x;
    int h=n/576, r=n-h*576, d=r/24, w=r-d*24;
    int np=(h+1)*676+(d+1)*26+(w+1);
    float qs  = g_xq[bc*NSP+n];       // q * log2e/8
    float bkc = __ldg(bk+c), bvc = __ldg(bv+c);
    float qbk = qs*bkc;
    const float* Kp = g_xk + (size_t)bc*NPAD + np;
    const float* Vp = g_xv + (size_t)bc*NPAD + np;
    float den=0.f, num=0.f, dens=0.f;
    #pragma unroll
    for (int m=0;m<5;m++){
        float e = ex2f_(qs*__ldg(mk+c*5+m));
        den += e;
        num  = fmaf(e, __ldg(mv+c*5+m), num);
    }
    #pragma unroll
    for (int j=0;j<27;j++){
        int dz=j/9, rr=j-dz*9, dy=rr/3, dx=rr-dy*3;
        int off=(dz-1)*676+(dy-1)*26+(dx-1);
        float kv=__ldg(Kp+off), vv=__ldg(Vp+off);
        float e = ex2f_(fmaf(qs,kv,qbk));
        dens += e;
        num   = fmaf(e,vv,num);
    }
    num = fmaf(bvc,dens,num);
    g_attn[bc*NSP+n] = num * rcpf_(den+dens);
}

// ---------------- Phase C: gate + blend + fixed-point channel-sum atomics ----------------
__global__ __launch_bounds__(256) void gate_kernel(
    const float* __restrict__ x, const float* __restrict__ Wg,
    const float* __restrict__ bg, float* __restrict__ out)
{
    __shared__ float xs[64][33];
    __shared__ float as[64][33];
    __shared__ float Wb[64][65];
    __shared__ float ssum[64];
    int b=blockIdx.y, n0=blockIdx.x*32, tid=threadIdx.x;
    if (tid<64) ssum[tid]=0.f;
    for (int i=tid;i<2048;i+=256){
        int cc=i>>5, nl=i&31;
        xs[cc][nl]=x[(b*64+cc)*NSP+n0+nl];
        as[cc][nl]=g_attn[(b*64+cc)*NSP+n0+nl];
    }
    int obase=(tid>>4)<<2, nb=(tid&15)<<1;
    float acc[4][2]={};
    for (int half=0;half<2;half++){
        __syncthreads();
        for (int i=tid;i<4096;i+=256) Wb[i>>6][i&63]=Wg[(i>>6)*128 + half*64 + (i&63)];
        __syncthreads();
        #pragma unroll 4
        for (int cc=0;cc<64;cc++){
            float s0 = half ? as[cc][nb]   : xs[cc][nb];
            float s1 = half ? as[cc][nb+1] : xs[cc][nb+1];
            #pragma unroll
            for (int i=0;i<4;i++){
                float wv=Wb[obase+i][cc];
                acc[i][0]=fmaf(wv,s0,acc[i][0]);
                acc[i][1]=fmaf(wv,s1,acc[i][1]);
            }
        }
    }
    #pragma unroll
    for (int i=0;i<4;i++){
        int o=obase+i;
        float bgo=__ldg(bg+o);
        float lsum=0.f;
        #pragma unroll
        for (int j=0;j<2;j++){
            float g  = sigmf_(acc[i][j]+bgo);
            float ov = g*as[o][nb+j] + (1.f-g)*xs[o][nb+j];
            out[(b*64+o)*NSP + n0+nb+j] = ov;
            lsum += ov;
        }
        atomicAdd(&ssum[o], lsum);
    }
    __syncthreads();
    if (tid<64){
        long long q = (long long)llrintf(ssum[tid]*FXS);   // deterministic integer accumulation
        atomicAdd((unsigned long long*)&g_acc[b*64+tid], (unsigned long long)q);
    }
}

// ---------------- Phase D: GRU memory update (1024 thr; reads fixed-point sums, resets) ----------------
__global__ __launch_bounds__(1024) void gru_kernel(
    const float* __restrict__ prev, const float* __restrict__ Wih, const float* __restrict__ Whh,
    const float* __restrict__ bih, const float* __restrict__ bhh, float* __restrict__ out_mem)
{
    __shared__ float mu[128], pm[128];
    int tid = threadIdx.x;
    if (tid < 128){
        mu[tid] = (float)((double)g_acc[tid] * (1.0/(16777216.0*13824.0)));
        pm[tid] = prev[tid];
    }
    __syncthreads();
    if (tid < 128) g_acc[tid] = 0;            // reset for next graph replay

    int w = tid >> 5, lane = tid & 31;
    #pragma unroll
    for (int rep = 0; rep < 4; rep++){
        int p2 = w + rep*32;          // 0..127
        int b = p2 >> 6, o = p2 & 63;
        float a0=0.f,a1=0.f,a2=0.f,a3=0.f,a4=0.f,a5=0.f;
        #pragma unroll
        for (int half = 0; half < 2; half++){
            int cc = lane + half*32;
            float m  = mu[b*64+cc];
            float pv = pm[b*64+cc];
            a0 = fmaf(__ldg(Wih + o*64        + cc), m,  a0);
            a1 = fmaf(__ldg(Wih + (64+o)*64   + cc), m,  a1);
            a2 = fmaf(__ldg(Wih + (128+o)*64  + cc), m,  a2);
            a3 = fmaf(__ldg(Whh + o*64        + cc), pv, a3);
            a4 = fmaf(__ldg(Whh + (64+o)*64   + cc), pv, a4);
            a5 = fmaf(__ldg(Whh + (128+o)*64  + cc), pv, a5);
        }
        #pragma unroll
        for (int off = 16; off; off >>= 1){
            a0 += __shfl_xor_sync(0xffffffffu, a0, off);
            a1 += __shfl_xor_sync(0xffffffffu, a1, off);
            a2 += __shfl_xor_sync(0xffffffffu, a2, off);
            a3 += __shfl_xor_sync(0xffffffffu, a3, off);
            a4 += __shfl_xor_sync(0xffffffffu, a4, off);
            a5 += __shfl_xor_sync(0xffffffffu, a5, off);
        }
        if (lane == 0){
            float gir = a0 + bih[o],     ghr = a3 + bhh[o];
            float giz = a1 + bih[64+o],  ghz = a4 + bhh[64+o];
            float gin = a2 + bih[128+o], ghn = a5 + bhh[128+o];
            float rg  = 1.f/(1.f+expf(-(gir+ghr)));
            float zg  = 1.f/(1.f+expf(-(giz+ghz)));
            float ng2 = tanhf(gin + rg*ghn);
            out_mem[p2] = (1.f-zg)*ng2 + zg*pm[b*64+o];
        }
    }
}

extern "C" void kernel_launch(void* const* d_in, const int* in_sizes, int n_in,
                              void* d_out, int out_size)
{
    const float* x   = (const float*)d_in[0];
    const float* prev= (const float*)d_in[1];
    const float* Wq  = (const float*)d_in[2];
    const float* bq  = (const float*)d_in[3];
    const float* Wk  = (const float*)d_in[4];
    const float* bk  = (const float*)d_in[5];
    const float* Wv  = (const float*)d_in[6];
    const float* bv  = (const float*)d_in[7];
    const float* mk  = (const float*)d_in[8];
    const float* mv  = (const float*)d_in[9];
    const float* Wg  = (const float*)d_in[10];
    const float* bg  = (const float*)d_in[11];
    const float* Wih = (const float*)d_in[12];
    const float* Whh = (const float*)d_in[13];
    const float* bih = (const float*)d_in[14];
    const float* bhh = (const float*)d_in[15];
    float* out = (float*)d_out;

    const int proj_smem = (4096 + 3*4096) * sizeof(float);   // 64KB
    static int attr_set = 0;
    if (!attr_set){
        cudaFuncSetAttribute(proj_kernel, cudaFuncAttributeMaxDynamicSharedMemorySize, proj_smem);
        attr_set = 1;
    }

    proj_kernel<<<dim3(216,2),256,proj_smem>>>(x,Wq,bq,Wk,Wv);
    attn_kernel<<<dim3(54,128),256>>>(bk,bv,mk,mv);
    gate_kernel<<<dim3(NBLK_GATE,2),256>>>(x,Wg,bg,out);
    gru_kernel<<<1,1024>>>(prev,Wih,Whh,bih,bhh,out + (size_t)BB*CCH*NSP);
}